// round 9
// baseline (speedup 1.0000x reference)
#include <cuda_runtime.h>

// SVConv2d: out[n,o,h,w] = bias[o] + sum_{ci,kh,kw} x[n,ci,h+kh-1,w+kw-1] * W[o,ci,kh,kw,h,w]
// N=8, Cin=Cout=32, K=3, H=W=64. Weight (151 MB) streams once -> DRAM-bound.
// R9: R8 skeleton (SPLIT=2, CPB=2, 1024 blocks, padded x planes, double-
// buffered weight regs) with (a) vectorized build_xpad (4 px/thread,
// LDG.128/STG.128) + tiny border kernel, (b) weight prefetch interleaved
// per-tap into the FMA stream so x L1-hits don't queue behind 18 DRAM
// misses in the L1tex FIFO.

typedef unsigned long long ull;

#define HW 4096
#define PD 66            // padded spatial dim
#define PP (PD * PD)     // 4356
#define SPLIT 2
#define CPB 2

// scratch (allocation-free: __device__ globals)
__device__ float4 g_xp0[32 * PP];              // (cin, 66, 66) n0..3 : 2.2 MB
__device__ float4 g_xp1[32 * PP];              // (cin, 66, 66) n4..7 : 2.2 MB
__device__ float g_part[SPLIT * 8 * 32 * HW];  // partial sums : 8 MB

__device__ __forceinline__ ull pack2(float a, float b) {
    ull r; asm("mov.b64 %0, {%1, %2};" : "=l"(r) : "f"(a), "f"(b)); return r;
}
__device__ __forceinline__ void fma2(ull& d, ull a, ull b) {
    asm("fma.rn.f32x2 %0, %1, %2, %0;" : "+l"(d) : "l"(a), "l"(b));
}
__device__ __forceinline__ float2 unpack2(ull v) {
    float x, y; asm("mov.b64 {%0, %1}, %2;" : "=f"(x), "=f"(y) : "l"(v));
    return make_float2(x, y);
}

// ---- kernel 1a: zero the padded borders (260 cells per cin) ----
__global__ __launch_bounds__(256) void zero_border() {
    int idx = blockIdx.x * 256 + threadIdx.x;      // < 32 * 260
    if (idx >= 32 * 260) return;
    int cin = idx / 260, r = idx - cin * 260;
    int hp, wp;
    if (r < 66)       { hp = 0;            wp = r; }
    else if (r < 132) { hp = 65;           wp = r - 66; }
    else if (r < 196) { hp = r - 132 + 1;  wp = 0; }
    else              { hp = r - 196 + 1;  wp = 65; }
    float4 z = make_float4(0.f, 0.f, 0.f, 0.f);
    g_xp0[cin * PP + hp * PD + wp] = z;
    g_xp1[cin * PP + hp * PD + wp] = z;
}

// ---- kernel 1b: interior transpose, 4 pixels/thread, vector loads/stores ----
__global__ __launch_bounds__(256) void build_xpad(const float* __restrict__ x) {
    int idx = blockIdx.x * 256 + threadIdx.x;      // < 32*64*16 = 32768
    if (idx >= 32 * 64 * 16) return;
    int cin = idx >> 10;
    int rem = idx & 1023;
    int h = rem >> 4;
    int w4 = (rem & 15) * 4;

    float4 v[8];
#pragma unroll
    for (int n = 0; n < 8; n++)
        v[n] = *(const float4*)(x + (size_t)(n * 32 + cin) * HW + h * 64 + w4);

    float4* p0 = g_xp0 + (size_t)cin * PP + (h + 1) * PD + (w4 + 1);
    float4* p1 = g_xp1 + (size_t)cin * PP + (h + 1) * PD + (w4 + 1);
#pragma unroll
    for (int j = 0; j < 4; j++) {
        const float* f = (const float*)v;          // v[n] component j
        p0[j] = make_float4(((const float*)&v[0])[j], ((const float*)&v[1])[j],
                            ((const float*)&v[2])[j], ((const float*)&v[3])[j]);
        p1[j] = make_float4(((const float*)&v[4])[j], ((const float*)&v[5])[j],
                            ((const float*)&v[6])[j], ((const float*)&v[7])[j]);
        (void)f;
    }
}

// load 18 weights (9 taps x 2 couts) for one cin into registers
__device__ __forceinline__ void loadW(float* wb, const float* wp) {
#pragma unroll
    for (int t = 0; t < 9; t++) {
        wb[t] = __ldcs(wp + t * HW);
        wb[9 + t] = __ldcs(wp + (size_t)(32 * 9) * HW + t * HW);
    }
}

// consume one cin (weights in wcur) while prefetching the next cin's weights
// into wnext from wp_next — interleaved per tap so x L1-hits stay shallow in
// the L1tex queue.
__device__ __forceinline__ void stageCP(const float* wcur, float* wnext,
                                        const float* wp_next,
                                        const float4* xb0, const float4* xb1,
                                        ull acc[CPB][4]) {
#pragma unroll
    for (int t = 0; t < 9; t++) {
        wnext[t] = __ldcs(wp_next + t * HW);
        wnext[9 + t] = __ldcs(wp_next + (size_t)(32 * 9) * HW + t * HW);
        const int off = (t / 3 - 1) * PD + (t % 3 - 1);  // compile-time
        float4 lo = __ldg(xb0 + off);
        float4 hi = __ldg(xb1 + off);
        ull xq0 = pack2(lo.x, lo.y);
        ull xq1 = pack2(lo.z, lo.w);
        ull xq2 = pack2(hi.x, hi.y);
        ull xq3 = pack2(hi.z, hi.w);
        ull wd0 = pack2(wcur[t], wcur[t]);
        ull wd1 = pack2(wcur[9 + t], wcur[9 + t]);
        fma2(acc[0][0], wd0, xq0);
        fma2(acc[0][1], wd0, xq1);
        fma2(acc[0][2], wd0, xq2);
        fma2(acc[0][3], wd0, xq3);
        fma2(acc[1][0], wd1, xq0);
        fma2(acc[1][1], wd1, xq1);
        fma2(acc[1][2], wd1, xq2);
        fma2(acc[1][3], wd1, xq3);
    }
}

// ---- kernel 2: main. block (32,4); warp = 32 consecutive w; no smem/barriers ----
__global__ __launch_bounds__(128, 5) void svconv_main(const float* __restrict__ wt_g) {
    const int lane = threadIdx.x, row = threadIdx.y;
    const int px = blockIdx.x * 32 + lane;
    const int py = blockIdx.y * 4 + row;
    const int c0 = (blockIdx.z & 15) * CPB;        // cout group (2 couts)
    const int s = blockIdx.z >> 4;                 // cin half

    ull acc[CPB][4];
#pragma unroll
    for (int c = 0; c < CPB; c++)
#pragma unroll
        for (int j = 0; j < 4; j++) acc[c][j] = 0ull;

    const float4* xb0 = g_xp0 + (size_t)(s * 16) * PP + (py + 1) * PD + (px + 1);
    const float4* xb1 = g_xp1 + (size_t)(s * 16) * PP + (py + 1) * PD + (px + 1);
    const float* wpc = wt_g + (size_t)(c0 * 32 + s * 16) * 9 * HW + py * 64 + px;

    float wA[18], wB[18];
    loadW(wA, wpc);                                 // cin 0

#pragma unroll 1
    for (int ci = 0; ci < 16; ci += 2) {
        // consume ci (wA), prefetch ci+1 -> wB
        stageCP(wA, wB, wpc + (size_t)9 * HW, xb0, xb1, acc);
        xb0 += PP; xb1 += PP;
        // consume ci+1 (wB), prefetch ci+2 -> wA (clamped in-bounds on last)
        const float* pn = (ci + 2 < 16) ? wpc + (size_t)18 * HW : wpc;
        stageCP(wB, wA, pn, xb0, xb1, acc);
        xb0 += PP; xb1 += PP;
        wpc += (size_t)18 * HW;                    // advance 2 cins
    }

    // write partials (no bias here), coalesced along w
    float* pb = g_part + (size_t)s * (8 * 32 * HW) + (size_t)c0 * HW + py * 64 + px;
#pragma unroll
    for (int c = 0; c < CPB; c++)
#pragma unroll
        for (int j = 0; j < 4; j++) {
            float2 v = unpack2(acc[c][j]);
            int n0 = 2 * j, n1 = 2 * j + 1;
            pb[(((size_t)n0 * 32) + c) * HW] = v.x;
            pb[(((size_t)n1 * 32) + c) * HW] = v.y;
        }
}

// ---- kernel 3: reduce partials + bias ----
__global__ __launch_bounds__(256) void reduce_out(const float* __restrict__ bias,
                                                  float* __restrict__ out) {
    int idx = blockIdx.x * 256 + threadIdx.x;      // < 8*32*4096
    int o = (idx >> 12) & 31;
    out[idx] = g_part[idx] + g_part[idx + 8 * 32 * HW] + bias[o];
}

extern "C" void kernel_launch(void* const* d_in, const int* in_sizes, int n_in,
                              void* d_out, int out_size) {
    const float* x = (const float*)d_in[0];
    const float* wgt = (const float*)d_in[1];
    const float* bias = (const float*)d_in[2];
    float* out = (float*)d_out;

    zero_border<<<(32 * 260 + 255) / 256, 256>>>();
    build_xpad<<<(32 * 64 * 16 + 255) / 256, 256>>>(x);
    dim3 grid(2, 16, 16 * SPLIT);                  // 1024 blocks
    dim3 block(32, 4);                             // 128 threads
    svconv_main<<<grid, block>>>(wgt);
    reduce_out<<<(8 * 32 * HW) / 256, 256>>>(bias, out);
}

// round 10
// speedup vs baseline: 1.1058x; 1.1058x over previous
#include <cuda_runtime.h>

// SVConv2d: out[n,o,h,w] = bias[o] + sum_{ci,kh,kw} x[n,ci,h+kh-1,w+kw-1] * W[o,ci,kh,kw,h,w]
// N=8, Cin=Cout=32, K=3, H=W=64. Weight (151 MB) streams once -> DRAM-bound.
// R10: main kernel = R8 verbatim (upfront loadW burst -> high MLP; the R9
// per-tap interleave regressed and is reverted). Side kernels vectorized:
// build_xpad 4px/thread LDG.128/STG.128 + border kernel, reduce_out float4.

typedef unsigned long long ull;

#define HW 4096
#define PD 66            // padded spatial dim
#define PP (PD * PD)     // 4356
#define SPLIT 2
#define CPB 2

// scratch (allocation-free: __device__ globals)
__device__ float4 g_xp0[32 * PP];              // (cin, 66, 66) n0..3 : 2.2 MB
__device__ float4 g_xp1[32 * PP];              // (cin, 66, 66) n4..7 : 2.2 MB
__device__ float g_part[SPLIT * 8 * 32 * HW];  // partial sums : 8 MB

__device__ __forceinline__ ull pack2(float a, float b) {
    ull r; asm("mov.b64 %0, {%1, %2};" : "=l"(r) : "f"(a), "f"(b)); return r;
}
__device__ __forceinline__ void fma2(ull& d, ull a, ull b) {
    asm("fma.rn.f32x2 %0, %1, %2, %0;" : "+l"(d) : "l"(a), "l"(b));
}
__device__ __forceinline__ float2 unpack2(ull v) {
    float x, y; asm("mov.b64 {%0, %1}, %2;" : "=f"(x), "=f"(y) : "l"(v));
    return make_float2(x, y);
}

// ---- kernel 1a: zero the padded borders (260 cells per cin) ----
__global__ __launch_bounds__(256) void zero_border() {
    int idx = blockIdx.x * 256 + threadIdx.x;      // < 32 * 260
    if (idx >= 32 * 260) return;
    int cin = idx / 260, r = idx - cin * 260;
    int hp, wp;
    if (r < 66)       { hp = 0;            wp = r; }
    else if (r < 132) { hp = 65;           wp = r - 66; }
    else if (r < 196) { hp = r - 132 + 1;  wp = 0; }
    else              { hp = r - 196 + 1;  wp = 65; }
    float4 z = make_float4(0.f, 0.f, 0.f, 0.f);
    g_xp0[cin * PP + hp * PD + wp] = z;
    g_xp1[cin * PP + hp * PD + wp] = z;
}

// ---- kernel 1b: interior transpose, 4 pixels/thread, vector loads/stores ----
__global__ __launch_bounds__(256) void build_xpad(const float* __restrict__ x) {
    int idx = blockIdx.x * 256 + threadIdx.x;      // < 32*64*16 = 32768
    if (idx >= 32 * 64 * 16) return;
    int cin = idx >> 10;
    int rem = idx & 1023;
    int h = rem >> 4;
    int w4 = (rem & 15) * 4;

    float4 v[8];
#pragma unroll
    for (int n = 0; n < 8; n++)
        v[n] = *(const float4*)(x + (size_t)(n * 32 + cin) * HW + h * 64 + w4);

    float4* p0 = g_xp0 + (size_t)cin * PP + (h + 1) * PD + (w4 + 1);
    float4* p1 = g_xp1 + (size_t)cin * PP + (h + 1) * PD + (w4 + 1);
#pragma unroll
    for (int j = 0; j < 4; j++) {
        p0[j] = make_float4(((const float*)&v[0])[j], ((const float*)&v[1])[j],
                            ((const float*)&v[2])[j], ((const float*)&v[3])[j]);
        p1[j] = make_float4(((const float*)&v[4])[j], ((const float*)&v[5])[j],
                            ((const float*)&v[6])[j], ((const float*)&v[7])[j]);
    }
}

// load 18 weights (9 taps x 2 couts) for one cin into registers (one burst)
__device__ __forceinline__ void loadW(float* wb, const float* wp) {
#pragma unroll
    for (int t = 0; t < 9; t++) {
        wb[t] = __ldcs(wp + t * HW);
        wb[9 + t] = __ldcs(wp + (size_t)(32 * 9) * HW + t * HW);
    }
}

// consume one cin: 18 x-load quads worth of FMAs with registered weights
__device__ __forceinline__ void fmaTaps(const float* wb,
                                        const float4* xb0, const float4* xb1,
                                        ull acc[CPB][4]) {
#pragma unroll
    for (int t = 0; t < 9; t++) {
        const int off = (t / 3 - 1) * PD + (t % 3 - 1);  // compile-time
        float4 lo = __ldg(xb0 + off);
        float4 hi = __ldg(xb1 + off);
        ull xq0 = pack2(lo.x, lo.y);
        ull xq1 = pack2(lo.z, lo.w);
        ull xq2 = pack2(hi.x, hi.y);
        ull xq3 = pack2(hi.z, hi.w);
        ull wd0 = pack2(wb[t], wb[t]);
        ull wd1 = pack2(wb[9 + t], wb[9 + t]);
        fma2(acc[0][0], wd0, xq0);
        fma2(acc[0][1], wd0, xq1);
        fma2(acc[0][2], wd0, xq2);
        fma2(acc[0][3], wd0, xq3);
        fma2(acc[1][0], wd1, xq0);
        fma2(acc[1][1], wd1, xq1);
        fma2(acc[1][2], wd1, xq2);
        fma2(acc[1][3], wd1, xq3);
    }
}

// ---- kernel 2: main. block (32,4); warp = 32 consecutive w; no smem/barriers ----
__global__ __launch_bounds__(128) void svconv_main(const float* __restrict__ wt_g) {
    const int lane = threadIdx.x, row = threadIdx.y;
    const int px = blockIdx.x * 32 + lane;
    const int py = blockIdx.y * 4 + row;
    const int c0 = (blockIdx.z & 15) * CPB;        // cout group (2 couts)
    const int s = blockIdx.z >> 4;                 // cin half

    ull acc[CPB][4];
#pragma unroll
    for (int c = 0; c < CPB; c++)
#pragma unroll
        for (int j = 0; j < 4; j++) acc[c][j] = 0ull;

    const float4* xb0 = g_xp0 + (size_t)(s * 16) * PP + (py + 1) * PD + (px + 1);
    const float4* xb1 = g_xp1 + (size_t)(s * 16) * PP + (py + 1) * PD + (px + 1);
    const float* wp = wt_g + (size_t)(c0 * 32 + s * 16) * 9 * HW + py * 64 + px;

    float wA[18], wB[18];
    loadW(wA, wp);                                  // cin 0

#pragma unroll 1
    for (int ci = 0; ci < 16; ci += 2) {
        // prefetch cin+1 (burst), then consume cin
        loadW(wB, wp + (size_t)9 * HW);
        fmaTaps(wA, xb0, xb1, acc);
        xb0 += PP; xb1 += PP;

        // prefetch cin+2 (burst, clamped in-bounds on last), then consume cin+1
        const float* p2 = wp + (size_t)(ci + 2 < 16 ? 2 : 0) * 9 * HW;
        loadW(wA, p2);
        fmaTaps(wB, xb0, xb1, acc);
        xb0 += PP; xb1 += PP;

        wp += (size_t)18 * HW;                     // advance 2 cins
    }

    // write partials (no bias here), coalesced along w
    float* pb = g_part + (size_t)s * (8 * 32 * HW) + (size_t)c0 * HW + py * 64 + px;
#pragma unroll
    for (int c = 0; c < CPB; c++)
#pragma unroll
        for (int j = 0; j < 4; j++) {
            float2 v = unpack2(acc[c][j]);
            int n0 = 2 * j, n1 = 2 * j + 1;
            pb[(((size_t)n0 * 32) + c) * HW] = v.x;
            pb[(((size_t)n1 * 32) + c) * HW] = v.y;
        }
}

// ---- kernel 3: reduce partials + bias (float4 vectorized) ----
__global__ __launch_bounds__(256) void reduce_out(const float* __restrict__ bias,
                                                  float4* __restrict__ out) {
    int idx = blockIdx.x * 256 + threadIdx.x;      // < 8*32*4096/4 = 262144
    int o = (idx >> 10) & 31;                      // 1024 float4 per (n,o) plane
    const float4* p0 = (const float4*)g_part;
    float4 a = __ldcs(p0 + idx);
    float4 b = __ldcs(p0 + idx + (8 * 32 * HW) / 4);
    float bi = __ldg(bias + o);
    out[idx] = make_float4(a.x + b.x + bi, a.y + b.y + bi,
                           a.z + b.z + bi, a.w + b.w + bi);
}

extern "C" void kernel_launch(void* const* d_in, const int* in_sizes, int n_in,
                              void* d_out, int out_size) {
    const float* x = (const float*)d_in[0];
    const float* wgt = (const float*)d_in[1];
    const float* bias = (const float*)d_in[2];
    float4* out = (float4*)d_out;

    zero_border<<<(32 * 260 + 255) / 256, 256>>>();
    build_xpad<<<(32 * 64 * 16 + 255) / 256, 256>>>(x);
    dim3 grid(2, 16, 16 * SPLIT);                  // 1024 blocks
    dim3 block(32, 4);                             // 128 threads
    svconv_main<<<grid, block>>>(wgt);
    reduce_out<<<(8 * 32 * HW / 4) / 256, 256>>>(bias, out);
}

// round 11
// speedup vs baseline: 1.2684x; 1.1471x over previous
#include <cuda_runtime.h>

// SVConv2d: out[n,o,h,w] = bias[o] + sum_{ci,kh,kw} x[n,ci,h+kh-1,w+kw-1] * W[o,ci,kh,kw,h,w]
// N=8, Cin=Cout=32, K=3, H=W=64. Weight (151 MB) streams once -> DRAM-bound.
// R11: drop the partials buffer + reduce kernel. out is initialized to bias,
// then both cin-halves atomicAdd (REDG) their contributions directly. Saves
// ~20 MB of DRAM traffic and a whole kernel launch. Main loop = R8's proven
// burst-prefetch structure (upfront 18-load loadW, double-buffered).

typedef unsigned long long ull;

#define HW 4096
#define PD 66            // padded spatial dim
#define PP (PD * PD)     // 4356
#define SPLIT 2
#define CPB 2

// scratch (allocation-free: __device__ globals)
__device__ float4 g_xp0[32 * PP];              // (cin, 66, 66) n0..3 : 2.2 MB
__device__ float4 g_xp1[32 * PP];              // (cin, 66, 66) n4..7 : 2.2 MB

__device__ __forceinline__ ull pack2(float a, float b) {
    ull r; asm("mov.b64 %0, {%1, %2};" : "=l"(r) : "f"(a), "f"(b)); return r;
}
__device__ __forceinline__ void fma2(ull& d, ull a, ull b) {
    asm("fma.rn.f32x2 %0, %1, %2, %0;" : "+l"(d) : "l"(a), "l"(b));
}
__device__ __forceinline__ float2 unpack2(ull v) {
    float x, y; asm("mov.b64 {%0, %1}, %2;" : "=f"(x), "=f"(y) : "l"(v));
    return make_float2(x, y);
}

// ---- kernel 1a: zero the padded borders (260 cells per cin) ----
__global__ __launch_bounds__(256) void zero_border() {
    int idx = blockIdx.x * 256 + threadIdx.x;      // < 32 * 260
    if (idx >= 32 * 260) return;
    int cin = idx / 260, r = idx - cin * 260;
    int hp, wp;
    if (r < 66)       { hp = 0;            wp = r; }
    else if (r < 132) { hp = 65;           wp = r - 66; }
    else if (r < 196) { hp = r - 132 + 1;  wp = 0; }
    else              { hp = r - 196 + 1;  wp = 65; }
    float4 z = make_float4(0.f, 0.f, 0.f, 0.f);
    g_xp0[cin * PP + hp * PD + wp] = z;
    g_xp1[cin * PP + hp * PD + wp] = z;
}

// ---- kernel 1b: interior transpose, 4 pixels/thread, vector loads/stores ----
__global__ __launch_bounds__(256) void build_xpad(const float* __restrict__ x) {
    int idx = blockIdx.x * 256 + threadIdx.x;      // < 32*64*16 = 32768
    if (idx >= 32 * 64 * 16) return;
    int cin = idx >> 10;
    int rem = idx & 1023;
    int h = rem >> 4;
    int w4 = (rem & 15) * 4;

    float4 v[8];
#pragma unroll
    for (int n = 0; n < 8; n++)
        v[n] = *(const float4*)(x + (size_t)(n * 32 + cin) * HW + h * 64 + w4);

    float4* p0 = g_xp0 + (size_t)cin * PP + (h + 1) * PD + (w4 + 1);
    float4* p1 = g_xp1 + (size_t)cin * PP + (h + 1) * PD + (w4 + 1);
#pragma unroll
    for (int j = 0; j < 4; j++) {
        p0[j] = make_float4(((const float*)&v[0])[j], ((const float*)&v[1])[j],
                            ((const float*)&v[2])[j], ((const float*)&v[3])[j]);
        p1[j] = make_float4(((const float*)&v[4])[j], ((const float*)&v[5])[j],
                            ((const float*)&v[6])[j], ((const float*)&v[7])[j]);
    }
}

// ---- kernel 1c: initialize out with bias ----
__global__ __launch_bounds__(256) void init_out(const float* __restrict__ bias,
                                                float4* __restrict__ out) {
    int idx = blockIdx.x * 256 + threadIdx.x;      // < 8*32*4096/4 = 262144
    float b = __ldg(bias + ((idx >> 10) & 31));
    out[idx] = make_float4(b, b, b, b);
}

// load 18 weights (9 taps x 2 couts) for one cin into registers (one burst)
__device__ __forceinline__ void loadW(float* wb, const float* wp) {
#pragma unroll
    for (int t = 0; t < 9; t++) {
        wb[t] = __ldcs(wp + t * HW);
        wb[9 + t] = __ldcs(wp + (size_t)(32 * 9) * HW + t * HW);
    }
}

// consume one cin: 18 x-load quads worth of FMAs with registered weights
__device__ __forceinline__ void fmaTaps(const float* wb,
                                        const float4* xb0, const float4* xb1,
                                        ull acc[CPB][4]) {
#pragma unroll
    for (int t = 0; t < 9; t++) {
        const int off = (t / 3 - 1) * PD + (t % 3 - 1);  // compile-time
        float4 lo = __ldg(xb0 + off);
        float4 hi = __ldg(xb1 + off);
        ull xq0 = pack2(lo.x, lo.y);
        ull xq1 = pack2(lo.z, lo.w);
        ull xq2 = pack2(hi.x, hi.y);
        ull xq3 = pack2(hi.z, hi.w);
        ull wd0 = pack2(wb[t], wb[t]);
        ull wd1 = pack2(wb[9 + t], wb[9 + t]);
        fma2(acc[0][0], wd0, xq0);
        fma2(acc[0][1], wd0, xq1);
        fma2(acc[0][2], wd0, xq2);
        fma2(acc[0][3], wd0, xq3);
        fma2(acc[1][0], wd1, xq0);
        fma2(acc[1][1], wd1, xq1);
        fma2(acc[1][2], wd1, xq2);
        fma2(acc[1][3], wd1, xq3);
    }
}

// ---- kernel 2: main. block (32,4); warp = 32 consecutive w; no smem/barriers ----
__global__ __launch_bounds__(128) void svconv_main(const float* __restrict__ wt_g,
                                                   float* __restrict__ out) {
    const int lane = threadIdx.x, row = threadIdx.y;
    const int px = blockIdx.x * 32 + lane;
    const int py = blockIdx.y * 4 + row;
    const int c0 = (blockIdx.z & 15) * CPB;        // cout group (2 couts)
    const int s = blockIdx.z >> 4;                 // cin half

    ull acc[CPB][4];
#pragma unroll
    for (int c = 0; c < CPB; c++)
#pragma unroll
        for (int j = 0; j < 4; j++) acc[c][j] = 0ull;

    const float4* xb0 = g_xp0 + (size_t)(s * 16) * PP + (py + 1) * PD + (px + 1);
    const float4* xb1 = g_xp1 + (size_t)(s * 16) * PP + (py + 1) * PD + (px + 1);
    const float* wp = wt_g + (size_t)(c0 * 32 + s * 16) * 9 * HW + py * 64 + px;

    float wA[18], wB[18];
    loadW(wA, wp);                                  // cin 0

#pragma unroll 1
    for (int ci = 0; ci < 16; ci += 2) {
        // prefetch cin+1 (burst), then consume cin
        loadW(wB, wp + (size_t)9 * HW);
        fmaTaps(wA, xb0, xb1, acc);
        xb0 += PP; xb1 += PP;

        // prefetch cin+2 (burst, clamped in-bounds on last), then consume cin+1
        const float* p2 = wp + (size_t)(ci + 2 < 16 ? 2 : 0) * 9 * HW;
        loadW(wA, p2);
        fmaTaps(wB, xb0, xb1, acc);
        xb0 += PP; xb1 += PP;

        wp += (size_t)18 * HW;                     // advance 2 cins
    }

    // ---- epilogue: atomic accumulate into out (bias pre-added by init_out) ----
    float* ob = out + (size_t)c0 * HW + py * 64 + px;
#pragma unroll
    for (int c = 0; c < CPB; c++)
#pragma unroll
        for (int j = 0; j < 4; j++) {
            float2 v = unpack2(acc[c][j]);
            int n0 = 2 * j, n1 = 2 * j + 1;
            atomicAdd(ob + (((size_t)n0 * 32) + c) * HW, v.x);
            atomicAdd(ob + (((size_t)n1 * 32) + c) * HW, v.y);
        }
}

extern "C" void kernel_launch(void* const* d_in, const int* in_sizes, int n_in,
                              void* d_out, int out_size) {
    const float* x = (const float*)d_in[0];
    const float* wgt = (const float*)d_in[1];
    const float* bias = (const float*)d_in[2];
    float* out = (float*)d_out;

    zero_border<<<(32 * 260 + 255) / 256, 256>>>();
    build_xpad<<<(32 * 64 * 16 + 255) / 256, 256>>>(x);
    init_out<<<(8 * 32 * HW / 4) / 256, 256>>>(bias, (float4*)out);
    dim3 grid(2, 16, 16 * SPLIT);                  // 1024 blocks
    dim3 block(32, 4);                             // 128 threads
    svconv_main<<<grid, block>>>(wgt, out);
}